// round 14
// baseline (speedup 1.0000x reference)
#include <cuda_runtime.h>
#include <cuda_bf16.h>
#include <cuda_fp16.h>
#include <cstdint>
#include <math.h>

#define NN 100000
#define EE 1600000
#define GG 64
#define HH 128
#define OUTC 10
#define BN_EPS 1e-5f
#define NB_SCAN 98   // ceil(100000/1024)

#define ASW 132                  // padded row stride in u32 words

// ---- k_mlp_mma smem layout (dynamic) ----
#define AS_OFF 0                 // u32[128][132]
#define WS_OFF 67584             // u32[128][132]
#define SB1_OFF 135168
#define SB2_OFF 135680
#define SMEM_BYTES 136192

// ---------------- scratch (static device globals; no allocation) ----------------
__device__ __align__(256) float g_bufA[NN*HH];
__device__ __align__(256) float g_bufB[NN*HH];
__device__ __align__(256) float g_agg[3][NN*HH];    // slot 2 = shared layer-1 agg; slot br = per-branch
__device__ __align__(256) __half g_h16[2][NN*HH];   // fp16 copies of layer outputs (gather reads)
__device__ __align__(256) __half g_h16x[NN*HH];     // fp16 copy of x
// per mat (12): [n:128][256 bf16] : k 0-127 = hi, 128-255 = lo   (Wt[n][k] = W[k][n])
__device__ __align__(256) __nv_bfloat16 g_Wt[12*32768];
__device__ int g_deg[NN];
__device__ int g_rowstart[NN+1];
__device__ int g_cursor[NN];
__device__ int g_csrsrc[EE];
__device__ int g_bsum[NB_SCAN];
__device__ int g_gstart[GG+1];
__device__ int g_ctr[8];
__device__ __align__(16) float g_scale[3*HH];
__device__ __align__(16) float g_shift[3*HH];
__device__ double g_colsum[2*HH];
__device__ double g_colsq[2*HH];
__device__ float g_poolA[GG*HH];
__device__ float g_poolB[GG*HH];
__device__ float g_V[GG*HH];

// ---------------- helpers ----------------
__device__ __forceinline__ void mma16816(float* dd, uint32_t a0, uint32_t a1, uint32_t a2, uint32_t a3,
                                         uint32_t b0, uint32_t b1) {
    asm volatile(
        "mma.sync.aligned.m16n8k16.row.col.f32.bf16.bf16.f32 "
        "{%0,%1,%2,%3}, {%4,%5,%6,%7}, {%8,%9}, {%0,%1,%2,%3};\n"
        : "+f"(dd[0]), "+f"(dd[1]), "+f"(dd[2]), "+f"(dd[3])
        : "r"(a0), "r"(a1), "r"(a2), "r"(a3), "r"(b0), "r"(b1));
}
__device__ __forceinline__ uint32_t bf16pair(float x, float y) {
    __nv_bfloat162 h = __float22bfloat162_rn(make_float2(x, y));
    return *(uint32_t*)&h;
}
__device__ __forceinline__ float4 h4tof4(uint2 u) {
    __half2 p0 = *(__half2*)&u.x;
    __half2 p1 = *(__half2*)&u.y;
    float2 f0 = __half22float2(p0);
    float2 f1 = __half22float2(p1);
    return make_float4(f0.x, f0.y, f1.x, f1.y);
}
__device__ __forceinline__ uint2 f4toh4(float4 v) {
    __half2 a = __floats2half2_rn(v.x, v.y);
    __half2 b = __floats2half2_rn(v.z, v.w);
    return make_uint2(*(uint32_t*)&a, *(uint32_t*)&b);
}

// ---------------- CSR build ----------------
__global__ void k_init() {   // zero deg + affine identity + zero stats + counters
    int i = blockIdx.x*blockDim.x + threadIdx.x;
    if (i < NN) g_deg[i] = 0;
    if (blockIdx.x == 0) {
        int t = threadIdx.x;
        if (t < 3*HH) { g_scale[t] = 1.f; g_shift[t] = 0.f; }
        if (t < 2*HH) { g_colsum[t] = 0.0; g_colsq[t] = 0.0; }
        if (t < 8) g_ctr[t] = 0;
    }
}
__global__ void k_hist(const int* __restrict__ dst) {
    int e = blockIdx.x*blockDim.x + threadIdx.x;
    if (e < EE) atomicAdd(&g_deg[dst[e]], 1);
}
__global__ void k_scan1() {
    __shared__ int sm[1024];
    int tid = threadIdx.x;
    int i = blockIdx.x*1024 + tid;
    int v = (i < NN) ? g_deg[i] : 0;
    sm[tid] = v;
    __syncthreads();
    for (int off = 1; off < 1024; off <<= 1) {
        int t = (tid >= off) ? sm[tid-off] : 0;
        __syncthreads();
        sm[tid] += t;
        __syncthreads();
    }
    if (i < NN) g_rowstart[i] = sm[tid] - v;
    if (tid == 1023) g_bsum[blockIdx.x] = sm[1023];
}
__global__ void k_scan2() {
    __shared__ int sm[128];
    int t = threadIdx.x;
    int v = (t < NB_SCAN) ? g_bsum[t] : 0;
    sm[t] = v;
    __syncthreads();
    for (int off = 1; off < 128; off <<= 1) {
        int u = (t >= off) ? sm[t-off] : 0;
        __syncthreads();
        sm[t] += u;
        __syncthreads();
    }
    if (t < NB_SCAN) g_bsum[t] = sm[t] - v;
}
__global__ void k_scan3() {
    int i = blockIdx.x*blockDim.x + threadIdx.x;
    if (i < NN) {
        int v = g_rowstart[i] + g_bsum[i >> 10];
        g_rowstart[i] = v;
        g_cursor[i] = v;
    }
    if (i == 0) g_rowstart[NN] = EE;
}
__global__ void k_fill(const int* __restrict__ src, const int* __restrict__ dst) {
    int e = blockIdx.x*blockDim.x + threadIdx.x;
    if (e < EE) {
        int d = dst[e];
        int p = atomicAdd(&g_cursor[d], 1);
        g_csrsrc[p] = src[e];
    }
}
__global__ void k_gstart(const int* __restrict__ batch) {
    int t = threadIdx.x;
    if (t > GG) return;
    int lo = 0, hi = NN;
    while (lo < hi) { int mid = (lo+hi) >> 1; if (batch[mid] < t) lo = mid+1; else hi = mid; }
    g_gstart[t] = lo;
}
// convert x -> fp16
__global__ void k_xprep(const float* __restrict__ xp) {
    int i = blockIdx.x*blockDim.x + threadIdx.x;
    if (i >= NN*HH/4) return;
    float4 v = ((const float4*)xp)[i];
    ((uint2*)g_h16x)[i] = f4toh4(v);
}

// convert all 12 W matrices to transposed/split bf16: g_Wt[mat][n][k(hi) | 128+k(lo)]
__global__ void k_wprep(const float* __restrict__ W1a, const float* __restrict__ W2a,
                        const float* __restrict__ W1b, const float* __restrict__ W2b) {
    int m = blockIdx.x*blockDim.x + threadIdx.x;
    if (m >= 12*16384) return;
    int mat = m >> 14;
    int elem = m & 16383;
    int k = elem >> 7, n = elem & 127;
    int br = mat / 6, rem = mat % 6, l = rem >> 1, g = rem & 1;
    const float* W = g ? (br ? W2b : W2a) : (br ? W1b : W1a);
    float w = W[l*16384 + k*128 + n];
    __nv_bfloat16 hi = __float2bfloat16(w);
    __nv_bfloat16 lo = __float2bfloat16(w - __bfloat162float(hi));
    g_Wt[mat*32768 + n*256 + k]       = hi;
    g_Wt[mat*32768 + n*256 + 128 + k] = lo;
}

// ---------------- gathers (fp16 reads, 1 node per warp) ----------------
__global__ void k_gather1() {
    int gw = (blockIdx.x*blockDim.x + threadIdx.x) >> 5;
    int lane = threadIdx.x & 31;
    if (gw >= NN) return;
    const uint2* __restrict__ h2 = (const uint2*)g_h16x;
    int rs = g_rowstart[gw], re = g_rowstart[gw+1];
    float4 acc = h4tof4(h2[gw*32 + lane]);   // self term
    int j = rs;
    for (; j + 4 <= re; j += 4) {
        int s0 = g_csrsrc[j], s1 = g_csrsrc[j+1], s2 = g_csrsrc[j+2], s3 = g_csrsrc[j+3];
        float4 v0 = h4tof4(h2[s0*32 + lane]);
        float4 v1 = h4tof4(h2[s1*32 + lane]);
        float4 v2 = h4tof4(h2[s2*32 + lane]);
        float4 v3 = h4tof4(h2[s3*32 + lane]);
        acc.x += (v0.x + v1.x) + (v2.x + v3.x);
        acc.y += (v0.y + v1.y) + (v2.y + v3.y);
        acc.z += (v0.z + v1.z) + (v2.z + v3.z);
        acc.w += (v0.w + v1.w) + (v2.w + v3.w);
    }
    for (; j < re; j++) {
        int s = g_csrsrc[j];
        float4 v = h4tof4(h2[s*32 + lane]);
        acc.x += v.x; acc.y += v.y; acc.z += v.z; acc.w += v.w;
    }
    ((float4*)g_agg[2])[gw*32 + lane] = acc;
}
__global__ void k_gather2(int br) {
    int gw = (blockIdx.x*blockDim.x + threadIdx.x) >> 5;
    int lane = threadIdx.x & 31;
    if (gw >= NN) return;
    const uint2* __restrict__ h2 = (const uint2*)g_h16[br];
    int rs = g_rowstart[gw], re = g_rowstart[gw+1];
    float4 acc = h4tof4(h2[gw*32 + lane]);
    int j = rs;
    for (; j + 4 <= re; j += 4) {
        int s0 = g_csrsrc[j], s1 = g_csrsrc[j+1], s2 = g_csrsrc[j+2], s3 = g_csrsrc[j+3];
        float4 v0 = h4tof4(h2[s0*32 + lane]);
        float4 v1 = h4tof4(h2[s1*32 + lane]);
        float4 v2 = h4tof4(h2[s2*32 + lane]);
        float4 v3 = h4tof4(h2[s3*32 + lane]);
        acc.x += (v0.x + v1.x) + (v2.x + v3.x);
        acc.y += (v0.y + v1.y) + (v2.y + v3.y);
        acc.z += (v0.z + v1.z) + (v2.z + v3.z);
        acc.w += (v0.w + v1.w) + (v2.w + v3.w);
    }
    for (; j < re; j++) {
        int s = g_csrsrc[j];
        float4 v = h4tof4(h2[s*32 + lane]);
        acc.x += v.x; acc.y += v.y; acc.z += v.z; acc.w += v.w;
    }
    float4 sc = ((const float4*)(g_scale + br*HH))[lane];
    float4 sh = ((const float4*)(g_shift + br*HH))[lane];
    float cf = (float)(re - rs + 1);
    float4 o;
    o.x = acc.x*sc.x + cf*sh.x;
    o.y = acc.y*sc.y + cf*sh.y;
    o.z = acc.z*sc.z + cf*sh.z;
    o.w = acc.w*sc.w + cf*sh.w;
    ((float4*)g_agg[br])[gw*32 + lane] = o;
}

// ---------------- HMMA fused MLP + fused BN finalize (warp = 32 rows x 64 cols) ----------------
__global__ void __launch_bounds__(256, 1)
k_mlp_mma(int br, int aggSel, int wsel,
          const float* __restrict__ b1, const float* __restrict__ b2,
          const float* __restrict__ gamma, const float* __restrict__ beta, int cidx)
{
    extern __shared__ char smem[];
    uint32_t* A32 = (uint32_t*)(smem + AS_OFF);
    uint32_t* W32 = (uint32_t*)(smem + WS_OFF);
    float* sb1 = (float*)(smem + SB1_OFF);
    float* sb2 = (float*)(smem + SB2_OFF);
    const int tid = threadIdx.x, wid = tid >> 5, lane = tid & 31;
    const int g = lane >> 2, t4 = lane & 3;
    const int rg = wid >> 1;
    const int cg = wid & 1;
    const int rowbase = blockIdx.x * 128;
    const float* Agg = g_agg[aggSel];
    float* out = br ? g_bufB : g_bufA;
    __half* out16 = g_h16[br];
    const __nv_bfloat16* Wt1 = &g_Wt[(wsel + 0)*32768];
    const __nv_bfloat16* Wt2 = &g_Wt[(wsel + 1)*32768];

    if (tid < 128) { sb1[tid] = b1[tid]; sb2[tid] = b2[tid]; }

    // stage W1: 128 rows x 32 uint4 per row
    {
        const uint4* src = (const uint4*)Wt1;
#pragma unroll
        for (int i = 0; i < 16; i++) {
            int idx = tid + i*256;
            int r = idx >> 5, q = idx & 31;
            *(uint4*)&W32[r*ASW + q*4] = src[idx];
        }
    }
    // stage A from agg (warp per row, coalesced)
#pragma unroll
    for (int i = 0; i < 16; i++) {
        int r = wid + 8*i;
        int grow = rowbase + r;
        float4 v = (grow < NN) ? ((const float4*)Agg)[grow*32 + lane] : make_float4(0.f,0.f,0.f,0.f);
        uint32_t h01 = bf16pair(v.x, v.y);
        uint32_t h23 = bf16pair(v.z, v.w);
        float2 f01 = __bfloat1622float2(*(__nv_bfloat162*)&h01);
        float2 f23 = __bfloat1622float2(*(__nv_bfloat162*)&h23);
        uint32_t l01 = bf16pair(v.x - f01.x, v.y - f01.y);
        uint32_t l23 = bf16pair(v.z - f23.x, v.w - f23.y);
        *(uint2*)&A32[r*ASW + lane*2]      = make_uint2(h01, h23);
        *(uint2*)&A32[r*ASW + 64 + lane*2] = make_uint2(l01, l23);
    }
    __syncthreads();

    const int abase[3] = {0, 64, 0};
    const int wbase[3] = {0, 0, 64};
    const int r0 = rg*32 + g;
    const int ar0 = r0*ASW, ar1 = (r0+8)*ASW, ar2 = (r0+16)*ASW, ar3 = (r0+24)*ASW;

    float d0[8][4], d1[8][4];
#pragma unroll
    for (int nt = 0; nt < 8; nt++) {
        d0[nt][0]=0.f; d0[nt][1]=0.f; d0[nt][2]=0.f; d0[nt][3]=0.f;
        d1[nt][0]=0.f; d1[nt][1]=0.f; d1[nt][2]=0.f; d1[nt][3]=0.f;
    }

    // ---------- GEMM1 ----------
#pragma unroll
    for (int term = 0; term < 3; term++) {
#pragma unroll
        for (int s = 0; s < 8; s++) {
            int aw = abase[term] + s*8;
            int ww = wbase[term] + s*8;
            uint32_t a0 = A32[ar0 + aw + t4];
            uint32_t a1 = A32[ar1 + aw + t4];
            uint32_t a2 = A32[ar0 + aw + 4 + t4];
            uint32_t a3 = A32[ar1 + aw + 4 + t4];
            uint32_t a4 = A32[ar2 + aw + t4];
            uint32_t a5 = A32[ar3 + aw + t4];
            uint32_t a6 = A32[ar2 + aw + 4 + t4];
            uint32_t a7 = A32[ar3 + aw + 4 + t4];
#pragma unroll
            for (int nt = 0; nt < 8; nt++) {
                int n = cg*64 + nt*8 + g;
                uint32_t b0 = W32[n*ASW + ww + t4];
                uint32_t b1r = W32[n*ASW + ww + 4 + t4];
                mma16816(d0[nt], a0, a1, a2, a3, b0, b1r);
                mma16816(d1[nt], a4, a5, a6, a7, b0, b1r);
            }
        }
    }
    __syncthreads();   // all warps done reading W1

    // stage W2
    {
        const uint4* src = (const uint4*)Wt2;
#pragma unroll
        for (int i = 0; i < 16; i++) {
            int idx = tid + i*256;
            int r = idx >> 5, q = idx & 31;
            *(uint4*)&W32[r*ASW + q*4] = src[idx];
        }
    }
    // epilogue 1: relu(d + b1) -> hi/lo bf16 into A rows
#pragma unroll
    for (int nt = 0; nt < 8; nt++) {
        int c = cg*64 + nt*8 + t4*2;
        int w = c >> 1;
        float bv0 = sb1[c], bv1 = sb1[c+1];
#pragma unroll
        for (int hl = 0; hl < 2; hl++) {
            float* dd = hl ? d1[nt] : d0[nt];
            int rlo = hl ? ar2 : ar0;
            int rhi = hl ? ar3 : ar1;
            float v0 = dd[0] + bv0;
            float v1 = dd[1] + bv1;
            float v2 = dd[2] + bv0;
            float v3 = dd[3] + bv1;
            v0 = v0 > 0.f ? v0 : 0.f;
            v1 = v1 > 0.f ? v1 : 0.f;
            v2 = v2 > 0.f ? v2 : 0.f;
            v3 = v3 > 0.f ? v3 : 0.f;
            uint32_t h0 = bf16pair(v0, v1);
            uint32_t h1 = bf16pair(v2, v3);
            float2 f0 = __bfloat1622float2(*(__nv_bfloat162*)&h0);
            float2 f1 = __bfloat1622float2(*(__nv_bfloat162*)&h1);
            uint32_t l0 = bf16pair(v0 - f0.x, v1 - f0.y);
            uint32_t l1 = bf16pair(v2 - f1.x, v3 - f1.y);
            A32[rlo + w]      = h0;
            A32[rlo + 64 + w] = l0;
            A32[rhi + w]      = h1;
            A32[rhi + 64 + w] = l1;
            dd[0]=0.f; dd[1]=0.f; dd[2]=0.f; dd[3]=0.f;
        }
    }
    __syncthreads();

    // ---------- GEMM2 ----------
#pragma unroll
    for (int term = 0; term < 3; term++) {
#pragma unroll
        for (int s = 0; s < 8; s++) {
            int aw = abase[term] + s*8;
            int ww = wbase[term] + s*8;
            uint32_t a0 = A32[ar0 + aw + t4];
            uint32_t a1 = A32[ar1 + aw + t4];
            uint32_t a2 = A32[ar0 + aw + 4 + t4];
            uint32_t a3 = A32[ar1 + aw + 4 + t4];
            uint32_t a4 = A32[ar2 + aw + t4];
            uint32_t a5 = A32[ar3 + aw + t4];
            uint32_t a6 = A32[ar2 + aw + 4 + t4];
            uint32_t a7 = A32[ar3 + aw + 4 + t4];
#pragma unroll
            for (int nt = 0; nt < 8; nt++) {
                int n = cg*64 + nt*8 + g;
                uint32_t b0 = W32[n*ASW + ww + t4];
                uint32_t b1r = W32[n*ASW + ww + 4 + t4];
                mma16816(d0[nt], a0, a1, a2, a3, b0, b1r);
                mma16816(d1[nt], a4, a5, a6, a7, b0, b1r);
            }
        }
    }
    __syncthreads();   // done reading A (bf16) before fp32 overwrite

    // epilogue 2: relu(d + b2) -> fp32 into A region
    float* Af = (float*)A32;
    {
#pragma unroll
        for (int nt = 0; nt < 8; nt++) {
            int c = cg*64 + nt*8 + t4*2;
            float bv0 = sb2[c], bv1 = sb2[c+1];
#pragma unroll
            for (int hl = 0; hl < 2; hl++) {
                float* dd = hl ? d1[nt] : d0[nt];
                int rowA = rg*32 + g + (hl ? 16 : 0);
                int rowB = rowA + 8;
                float v0 = dd[0] + bv0;
                float v1 = dd[1] + bv1;
                float v2 = dd[2] + bv0;
                float v3 = dd[3] + bv1;
                v0 = v0 > 0.f ? v0 : 0.f;
                v1 = v1 > 0.f ? v1 : 0.f;
                v2 = v2 > 0.f ? v2 : 0.f;
                v3 = v3 > 0.f ? v3 : 0.f;
                if (rowbase + rowA >= NN) { v0 = 0.f; v1 = 0.f; }
                if (rowbase + rowB >= NN) { v2 = 0.f; v3 = 0.f; }
                *(float2*)&Af[rowA*ASW + c] = make_float2(v0, v1);
                *(float2*)&Af[rowB*ASW + c] = make_float2(v2, v3);
            }
        }
    }
    __syncthreads();

    // per-column stats (2 threads per column, 64 rows each)
    {
        int col = tid & 127;
        int half = tid >> 7;
        float s = 0.f, q = 0.f;
#pragma unroll 8
        for (int r = half*64; r < half*64 + 64; r++) {
            float x = Af[r*ASW + col];
            s += x; q += x*x;
        }
        atomicAdd(&g_colsum[br*HH + col], (double)s);
        atomicAdd(&g_colsq[br*HH + col], (double)q);
    }
    // coalesced store (warp per row): fp32 + fp16 copies
#pragma unroll
    for (int i = 0; i < 16; i++) {
        int r = wid + 8*i;
        int gr = rowbase + r;
        if (gr < NN) {
            float4 v = *(const float4*)&Af[r*ASW + lane*4];
            ((float4*)(out + gr*128))[lane] = v;
            ((uint2*)(out16 + gr*128))[lane] = f4toh4(v);
        }
    }

    // ---------- fused BN finalize: last block computes scale/shift ----------
    __syncthreads();
    int* flag = (int*)sb1;   // sb1 dead now
    __threadfence();
    if (tid == 0) {
        int prev = atomicAdd(&g_ctr[cidx], 1);
        flag[0] = (prev == (int)gridDim.x - 1) ? 1 : 0;
    }
    __syncthreads();
    if (flag[0]) {
        __threadfence();
        if (tid < HH) {
            int t = br*HH + tid;
            double mu  = g_colsum[t] / (double)NN;
            double var = g_colsq[t] / (double)NN - mu*mu;
            if (var < 0.0) var = 0.0;
            float inv = rsqrtf((float)var + BN_EPS);
            float s = gamma[tid] * inv;
            g_scale[t] = s;
            g_shift[t] = beta[tid] - (float)mu * s;
            g_colsum[t] = 0.0;
            g_colsq[t] = 0.0;
        }
    }
}

// ---------------- pool & heads ----------------
__global__ void k_pool2() {
    int g = blockIdx.x, br = blockIdx.y, c = threadIdx.x;
    const float* h = br ? g_bufB : g_bufA;
    float* pool = br ? g_poolB : g_poolA;
    int s = g_gstart[g], e = g_gstart[g+1];
    float sc = g_scale[br*HH + c], sh = g_shift[br*HH + c];
    float acc = 0.f;
    for (int n = s; n < e; n++) acc += h[n*128 + c];
    float cnt = (float)(e - s);
    float cl = cnt < 1.f ? 1.f : cnt;
    pool[g*128 + c] = (acc*sc + cnt*sh) / cl;
}
__global__ void k_head1(const float* __restrict__ lin1_w, const float* __restrict__ lin1_b,
                        const float* __restrict__ lin2_w, const float* __restrict__ lin2_b,
                        const float* __restrict__ disc_w, float* __restrict__ outp)
{
    __shared__ float px[128];
    __shared__ float cat[256];
    __shared__ float h1[128];
    __shared__ float zz[OUTC];
    int g = blockIdx.x;
    int c = threadIdx.x;
    px[c] = g_poolB[g*128 + c];
    cat[c] = g_poolA[g*128 + c];
    cat[128 + c] = px[c];
    __syncthreads();
    float acc = 0.f;
    for (int e = 0; e < 128; e++) acc += disc_w[c*128 + e] * px[e];
    g_V[g*128 + c] = acc;
    float a2 = lin1_b[c];
    for (int k = 0; k < 256; k++) a2 += cat[k] * lin1_w[k*128 + c];
    h1[c] = a2 > 0.f ? a2 : 0.f;
    __syncthreads();
    if (c < OUTC) {
        float z = lin2_b[c];
        for (int k = 0; k < 128; k++) z += h1[k] * lin2_w[k*OUTC + c];
        zz[c] = z;
    }
    __syncthreads();
    if (c == 0) {
        float m = -1e30f;
        for (int o = 0; o < OUTC; o++) m = fmaxf(m, zz[o]);
        float s = 0.f;
        for (int o = 0; o < OUTC; o++) s += expf(zz[o] - m);
        float lse = logf(s) + m;
        for (int o = 0; o < OUTC; o++) outp[g*OUTC + o] = zz[o] - lse;
    }
}
__global__ void k_head2(const float* __restrict__ disc_b, float* __restrict__ outp) {
    int wid = (blockIdx.x*blockDim.x + threadIdx.x) >> 5;
    int lane = threadIdx.x & 31;
    if (wid >= 2*GG) return;
    int which = wid >> 6;
    int g = wid & 63;
    int gs = (which == 0) ? g : (g == 32 ? 30 : 63 - g);
    const float* a = &g_poolB[g*128];
    const float* v = &g_V[gs*128];
    float s = 0.f;
    for (int e = lane; e < 128; e += 32) s += a[e] * v[e];
#pragma unroll
    for (int off = 16; off > 0; off >>= 1) s += __shfl_down_sync(0xffffffffu, s, off);
    if (lane == 0) outp[GG*OUTC + which*GG + g] = s + disc_b[0];
}

// ---------------- launch ----------------
extern "C" void kernel_launch(void* const* d_in, const int* in_sizes, int n_in,
                              void* d_out, int out_size)
{
    (void)in_sizes; (void)n_in; (void)out_size;
    const float* x     = (const float*)d_in[0];
    const int*   ei    = (const int*)d_in[1];
    const int*   src   = ei;
    const int*   dst   = ei + EE;
    const int*   batch = (const int*)d_in[2];
    const float* W1a = (const float*)d_in[3];  const float* b1a = (const float*)d_in[4];
    const float* W2a = (const float*)d_in[5];  const float* b2a = (const float*)d_in[6];
    const float* ga  = (const float*)d_in[7];  const float* bta = (const float*)d_in[8];
    const float* W1b = (const float*)d_in[9];  const float* b1b = (const float*)d_in[10];
    const float* W2b = (const float*)d_in[11]; const float* b2b = (const float*)d_in[12];
    const float* gb  = (const float*)d_in[13]; const float* btb = (const float*)d_in[14];
    const float* lin1_w = (const float*)d_in[15]; const float* lin1_b = (const float*)d_in[16];
    const float* lin2_w = (const float*)d_in[17]; const float* lin2_b = (const float*)d_in[18];
    const float* disc_w = (const float*)d_in[19]; const float* disc_b = (const float*)d_in[20];
    float* outp = (float*)d_out;

    cudaFuncSetAttribute(k_mlp_mma, cudaFuncAttributeMaxDynamicSharedMemorySize, SMEM_BYTES);

    // side stream + events for branch-B pipeline (created per call; host objects only)
    cudaStream_t sB;
    cudaStreamCreateWithFlags(&sB, cudaStreamNonBlocking);
    cudaEvent_t evFork, evJoin;
    cudaEventCreateWithFlags(&evFork, cudaEventDisableTiming);
    cudaEventCreateWithFlags(&evJoin, cudaEventDisableTiming);

    // CSR build + W/x prep on main stream
    k_init<<<(NN+391)/392, 392>>>();
    k_hist<<<(EE+255)/256, 256>>>(dst);
    k_scan1<<<NB_SCAN, 1024>>>();
    k_scan2<<<1, 128>>>();
    k_scan3<<<(NN+255)/256, 256>>>();
    k_fill<<<(EE+255)/256, 256>>>(src, dst);
    k_gstart<<<1, 96>>>(batch);
    k_wprep<<<768, 256>>>(W1a, W2a, W1b, W2b);
    k_xprep<<<(NN*HH/4 + 255)/256, 256>>>(x);

    const int mlp_bx = (NN + 127) / 128;
    const int gather_bx = (NN*32 + 255) / 256;   // 1 node per warp

    // shared layer-1 gather of x -> agg[2]
    k_gather1<<<gather_bx, 256>>>();

    // fork branch B
    cudaEventRecord(evFork, 0);
    cudaStreamWaitEvent(sB, evFork, 0);

    // branch A on main stream
    for (int l = 0; l < 3; l++) {
        if (l > 0) k_gather2<<<gather_bx, 256, 0, 0>>>(0);
        k_mlp_mma<<<mlp_bx, 256, SMEM_BYTES, 0>>>(0, (l == 0) ? 2 : 0, 0*6 + l*2,
            b1a + l*HH, b2a + l*HH, ga + l*HH, bta + l*HH, 0*3 + l);
    }
    // branch B on side stream
    for (int l = 0; l < 3; l++) {
        if (l > 0) k_gather2<<<gather_bx, 256, 0, sB>>>(1);
        k_mlp_mma<<<mlp_bx, 256, SMEM_BYTES, sB>>>(1, (l == 0) ? 2 : 1, 1*6 + l*2,
            b1b + l*HH, b2b + l*HH, gb + l*HH, btb + l*HH, 1*3 + l);
    }

    // join
    cudaEventRecord(evJoin, sB);
    cudaStreamWaitEvent(0, evJoin, 0);

    k_pool2<<<dim3(GG, 2), 128>>>();
    k_head1<<<GG, 128>>>(lin1_w, lin1_b, lin2_w, lin2_b, disc_w, outp);
    k_head2<<<16, 256>>>(disc_b, outp);
}

// round 15
// speedup vs baseline: 1.0703x; 1.0703x over previous
#include <cuda_runtime.h>
#include <cuda_bf16.h>
#include <cuda_fp16.h>
#include <cstdint>
#include <math.h>

#define NN 100000
#define EE 1600000
#define GG 64
#define HH 128
#define OUTC 10
#define BN_EPS 1e-5f
#define NB_SCAN 98   // ceil(100000/1024)

#define ASW 132                  // padded row stride in u32 words

// ---- k_mlp_mma smem layout (dynamic) ----
#define AS_OFF 0                 // u32[128][132]
#define WS_OFF 67584             // u32[128][132]
#define SB1_OFF 135168
#define SB2_OFF 135680
#define SMEM_BYTES 136192

// ---------------- scratch (static device globals; no allocation) ----------------
__device__ __align__(256) float g_agg[2][NN*HH];
__device__ __align__(256) __half g_h16[2][NN*HH];   // fp16 layer outputs (gather + pool reads)
__device__ __align__(256) __half g_h16x[NN*HH];     // fp16 copy of x
// per mat (12): [n:128][256 bf16] : k 0-127 = hi, 128-255 = lo   (Wt[n][k] = W[k][n])
__device__ __align__(256) __nv_bfloat16 g_Wt[12*32768];
__device__ int g_deg[NN];
__device__ int g_rowstart[NN+1];
__device__ int g_cursor[NN];
__device__ int g_csrsrc[EE];
__device__ int g_bsum[NB_SCAN];
__device__ int g_gstart[GG+1];
__device__ int g_ctr[8];
__device__ __align__(16) float g_scale[3*HH];
__device__ __align__(16) float g_shift[3*HH];
__device__ double g_colsum[2*HH];
__device__ double g_colsq[2*HH];
__device__ float g_poolA[GG*HH];
__device__ float g_poolB[GG*HH];
__device__ float g_V[GG*HH];

// ---------------- helpers ----------------
__device__ __forceinline__ void mma16816(float* dd, uint32_t a0, uint32_t a1, uint32_t a2, uint32_t a3,
                                         uint32_t b0, uint32_t b1) {
    asm volatile(
        "mma.sync.aligned.m16n8k16.row.col.f32.bf16.bf16.f32 "
        "{%0,%1,%2,%3}, {%4,%5,%6,%7}, {%8,%9}, {%0,%1,%2,%3};\n"
        : "+f"(dd[0]), "+f"(dd[1]), "+f"(dd[2]), "+f"(dd[3])
        : "r"(a0), "r"(a1), "r"(a2), "r"(a3), "r"(b0), "r"(b1));
}
__device__ __forceinline__ uint32_t bf16pair(float x, float y) {
    __nv_bfloat162 h = __float22bfloat162_rn(make_float2(x, y));
    return *(uint32_t*)&h;
}
__device__ __forceinline__ float4 h4tof4(uint2 u) {
    __half2 p0 = *(__half2*)&u.x;
    __half2 p1 = *(__half2*)&u.y;
    float2 f0 = __half22float2(p0);
    float2 f1 = __half22float2(p1);
    return make_float4(f0.x, f0.y, f1.x, f1.y);
}
__device__ __forceinline__ uint2 f4toh4(float4 v) {
    __half2 a = __floats2half2_rn(v.x, v.y);
    __half2 b = __floats2half2_rn(v.z, v.w);
    return make_uint2(*(uint32_t*)&a, *(uint32_t*)&b);
}

// ---------------- CSR build ----------------
__global__ void k_init() {   // zero deg + affine identity + zero stats + counters
    int i = blockIdx.x*blockDim.x + threadIdx.x;
    if (i < NN) g_deg[i] = 0;
    if (blockIdx.x == 0) {
        int t = threadIdx.x;
        if (t < 3*HH) { g_scale[t] = 1.f; g_shift[t] = 0.f; }
        if (t < 2*HH) { g_colsum[t] = 0.0; g_colsq[t] = 0.0; }
        if (t < 8) g_ctr[t] = 0;
    }
}
__global__ void k_hist(const int* __restrict__ dst) {
    int e = blockIdx.x*blockDim.x + threadIdx.x;
    if (e < EE) atomicAdd(&g_deg[dst[e]], 1);
}
__global__ void k_scan1() {
    __shared__ int sm[1024];
    int tid = threadIdx.x;
    int i = blockIdx.x*1024 + tid;
    int v = (i < NN) ? g_deg[i] : 0;
    sm[tid] = v;
    __syncthreads();
    for (int off = 1; off < 1024; off <<= 1) {
        int t = (tid >= off) ? sm[tid-off] : 0;
        __syncthreads();
        sm[tid] += t;
        __syncthreads();
    }
    if (i < NN) g_rowstart[i] = sm[tid] - v;
    if (tid == 1023) g_bsum[blockIdx.x] = sm[1023];
}
__global__ void k_scan2() {
    __shared__ int sm[128];
    int t = threadIdx.x;
    int v = (t < NB_SCAN) ? g_bsum[t] : 0;
    sm[t] = v;
    __syncthreads();
    for (int off = 1; off < 128; off <<= 1) {
        int u = (t >= off) ? sm[t-off] : 0;
        __syncthreads();
        sm[t] += u;
        __syncthreads();
    }
    if (t < NB_SCAN) g_bsum[t] = sm[t] - v;
}
__global__ void k_scan3() {
    int i = blockIdx.x*blockDim.x + threadIdx.x;
    if (i < NN) {
        int v = g_rowstart[i] + g_bsum[i >> 10];
        g_rowstart[i] = v;
        g_cursor[i] = v;
    }
    if (i == 0) g_rowstart[NN] = EE;
}
__global__ void k_fill(const int* __restrict__ src, const int* __restrict__ dst) {
    int e = blockIdx.x*blockDim.x + threadIdx.x;
    if (e < EE) {
        int d = dst[e];
        int p = atomicAdd(&g_cursor[d], 1);
        g_csrsrc[p] = src[e];
    }
}
__global__ void k_gstart(const int* __restrict__ batch) {
    int t = threadIdx.x;
    if (t > GG) return;
    int lo = 0, hi = NN;
    while (lo < hi) { int mid = (lo+hi) >> 1; if (batch[mid] < t) lo = mid+1; else hi = mid; }
    g_gstart[t] = lo;
}
// convert x -> fp16
__global__ void k_xprep(const float* __restrict__ xp) {
    int i = blockIdx.x*blockDim.x + threadIdx.x;
    if (i >= NN*HH/4) return;
    float4 v = ((const float4*)xp)[i];
    ((uint2*)g_h16x)[i] = f4toh4(v);
}

// convert all 12 W matrices to transposed/split bf16: g_Wt[mat][n][k(hi) | 128+k(lo)]
__global__ void k_wprep(const float* __restrict__ W1a, const float* __restrict__ W2a,
                        const float* __restrict__ W1b, const float* __restrict__ W2b) {
    int m = blockIdx.x*blockDim.x + threadIdx.x;
    if (m >= 12*16384) return;
    int mat = m >> 14;
    int elem = m & 16383;
    int k = elem >> 7, n = elem & 127;
    int br = mat / 6, rem = mat % 6, l = rem >> 1, g = rem & 1;
    const float* W = g ? (br ? W2b : W2a) : (br ? W1b : W1a);
    float w = W[l*16384 + k*128 + n];
    __nv_bfloat16 hi = __float2bfloat16(w);
    __nv_bfloat16 lo = __float2bfloat16(w - __bfloat162float(hi));
    g_Wt[mat*32768 + n*256 + k]       = hi;
    g_Wt[mat*32768 + n*256 + 128 + k] = lo;
}

// ---------------- gathers (fp16 reads, 1 node per warp) ----------------
__global__ void k_gather1() {
    int gw = (blockIdx.x*blockDim.x + threadIdx.x) >> 5;
    int lane = threadIdx.x & 31;
    if (gw >= NN) return;
    const uint2* __restrict__ h2 = (const uint2*)g_h16x;
    int rs = g_rowstart[gw], re = g_rowstart[gw+1];
    float4 acc = h4tof4(h2[gw*32 + lane]);   // self term
    int j = rs;
    for (; j + 4 <= re; j += 4) {
        int s0 = g_csrsrc[j], s1 = g_csrsrc[j+1], s2 = g_csrsrc[j+2], s3 = g_csrsrc[j+3];
        float4 v0 = h4tof4(h2[s0*32 + lane]);
        float4 v1 = h4tof4(h2[s1*32 + lane]);
        float4 v2 = h4tof4(h2[s2*32 + lane]);
        float4 v3 = h4tof4(h2[s3*32 + lane]);
        acc.x += (v0.x + v1.x) + (v2.x + v3.x);
        acc.y += (v0.y + v1.y) + (v2.y + v3.y);
        acc.z += (v0.z + v1.z) + (v2.z + v3.z);
        acc.w += (v0.w + v1.w) + (v2.w + v3.w);
    }
    for (; j < re; j++) {
        int s = g_csrsrc[j];
        float4 v = h4tof4(h2[s*32 + lane]);
        acc.x += v.x; acc.y += v.y; acc.z += v.z; acc.w += v.w;
    }
    ((float4*)g_agg[0])[gw*32 + lane] = acc;
}
__global__ void k_gather2() {
    int gw = (blockIdx.x*blockDim.x + threadIdx.x) >> 5;
    int lane = threadIdx.x & 31;
    if (gw >= NN) return;
    int br = blockIdx.y;
    const uint2* __restrict__ h2 = (const uint2*)g_h16[br];
    int rs = g_rowstart[gw], re = g_rowstart[gw+1];
    float4 acc = h4tof4(h2[gw*32 + lane]);
    int j = rs;
    for (; j + 4 <= re; j += 4) {
        int s0 = g_csrsrc[j], s1 = g_csrsrc[j+1], s2 = g_csrsrc[j+2], s3 = g_csrsrc[j+3];
        float4 v0 = h4tof4(h2[s0*32 + lane]);
        float4 v1 = h4tof4(h2[s1*32 + lane]);
        float4 v2 = h4tof4(h2[s2*32 + lane]);
        float4 v3 = h4tof4(h2[s3*32 + lane]);
        acc.x += (v0.x + v1.x) + (v2.x + v3.x);
        acc.y += (v0.y + v1.y) + (v2.y + v3.y);
        acc.z += (v0.z + v1.z) + (v2.z + v3.z);
        acc.w += (v0.w + v1.w) + (v2.w + v3.w);
    }
    for (; j < re; j++) {
        int s = g_csrsrc[j];
        float4 v = h4tof4(h2[s*32 + lane]);
        acc.x += v.x; acc.y += v.y; acc.z += v.z; acc.w += v.w;
    }
    float4 sc = ((const float4*)(g_scale + br*HH))[lane];
    float4 sh = ((const float4*)(g_shift + br*HH))[lane];
    float cf = (float)(re - rs + 1);
    float4 o;
    o.x = acc.x*sc.x + cf*sh.x;
    o.y = acc.y*sc.y + cf*sh.y;
    o.z = acc.z*sc.z + cf*sh.z;
    o.w = acc.w*sc.w + cf*sh.w;
    ((float4*)g_agg[br])[gw*32 + lane] = o;
}

// ---------------- HMMA fused MLP + fused BN finalize (warp = 32 rows x 64 cols) ----------------
// grid (mlp_bx, 2): blockIdx.y = branch. fp16-only output.
__global__ void __launch_bounds__(256, 1)
k_mlp_mma(int aggShared, int layer,
          const float* __restrict__ b1a_, const float* __restrict__ b2a_,
          const float* __restrict__ b1b_, const float* __restrict__ b2b_,
          const float* __restrict__ gA, const float* __restrict__ btA,
          const float* __restrict__ gB, const float* __restrict__ btB)
{
    extern __shared__ char smem[];
    uint32_t* A32 = (uint32_t*)(smem + AS_OFF);
    uint32_t* W32 = (uint32_t*)(smem + WS_OFF);
    float* sb1 = (float*)(smem + SB1_OFF);
    float* sb2 = (float*)(smem + SB2_OFF);
    const int tid = threadIdx.x, wid = tid >> 5, lane = tid & 31;
    const int g = lane >> 2, t4 = lane & 3;
    const int rg = wid >> 1;
    const int cg = wid & 1;
    const int br = blockIdx.y;
    const int rowbase = blockIdx.x * 128;
    const float* b1 = (br ? b1b_ : b1a_) + layer*HH;
    const float* b2 = (br ? b2b_ : b2a_) + layer*HH;
    const float* Agg = g_agg[aggShared ? 0 : br];
    __half* out16 = g_h16[br];
    const __nv_bfloat16* Wt1 = &g_Wt[(br*6 + layer*2 + 0)*32768];
    const __nv_bfloat16* Wt2 = &g_Wt[(br*6 + layer*2 + 1)*32768];

    if (tid < 128) { sb1[tid] = b1[tid]; sb2[tid] = b2[tid]; }

    // stage W1: 128 rows x 32 uint4 per row
    {
        const uint4* src = (const uint4*)Wt1;
#pragma unroll
        for (int i = 0; i < 16; i++) {
            int idx = tid + i*256;
            int r = idx >> 5, q = idx & 31;
            *(uint4*)&W32[r*ASW + q*4] = src[idx];
        }
    }
    // stage A from agg (warp per row, coalesced)
#pragma unroll
    for (int i = 0; i < 16; i++) {
        int r = wid + 8*i;
        int grow = rowbase + r;
        float4 v = (grow < NN) ? ((const float4*)Agg)[grow*32 + lane] : make_float4(0.f,0.f,0.f,0.f);
        uint32_t h01 = bf16pair(v.x, v.y);
        uint32_t h23 = bf16pair(v.z, v.w);
        float2 f01 = __bfloat1622float2(*(__nv_bfloat162*)&h01);
        float2 f23 = __bfloat1622float2(*(__nv_bfloat162*)&h23);
        uint32_t l01 = bf16pair(v.x - f01.x, v.y - f01.y);
        uint32_t l23 = bf16pair(v.z - f23.x, v.w - f23.y);
        *(uint2*)&A32[r*ASW + lane*2]      = make_uint2(h01, h23);
        *(uint2*)&A32[r*ASW + 64 + lane*2] = make_uint2(l01, l23);
    }
    __syncthreads();

    const int abase[3] = {0, 64, 0};
    const int wbase[3] = {0, 0, 64};
    const int r0 = rg*32 + g;
    const int ar0 = r0*ASW, ar1 = (r0+8)*ASW, ar2 = (r0+16)*ASW, ar3 = (r0+24)*ASW;

    float d0[8][4], d1[8][4];
#pragma unroll
    for (int nt = 0; nt < 8; nt++) {
        d0[nt][0]=0.f; d0[nt][1]=0.f; d0[nt][2]=0.f; d0[nt][3]=0.f;
        d1[nt][0]=0.f; d1[nt][1]=0.f; d1[nt][2]=0.f; d1[nt][3]=0.f;
    }

    // ---------- GEMM1 ----------
#pragma unroll
    for (int term = 0; term < 3; term++) {
#pragma unroll
        for (int s = 0; s < 8; s++) {
            int aw = abase[term] + s*8;
            int ww = wbase[term] + s*8;
            uint32_t a0 = A32[ar0 + aw + t4];
            uint32_t a1 = A32[ar1 + aw + t4];
            uint32_t a2 = A32[ar0 + aw + 4 + t4];
            uint32_t a3 = A32[ar1 + aw + 4 + t4];
            uint32_t a4 = A32[ar2 + aw + t4];
            uint32_t a5 = A32[ar3 + aw + t4];
            uint32_t a6 = A32[ar2 + aw + 4 + t4];
            uint32_t a7 = A32[ar3 + aw + 4 + t4];
#pragma unroll
            for (int nt = 0; nt < 8; nt++) {
                int n = cg*64 + nt*8 + g;
                uint32_t b0 = W32[n*ASW + ww + t4];
                uint32_t b1r = W32[n*ASW + ww + 4 + t4];
                mma16816(d0[nt], a0, a1, a2, a3, b0, b1r);
                mma16816(d1[nt], a4, a5, a6, a7, b0, b1r);
            }
        }
    }
    __syncthreads();   // all warps done reading W1

    // stage W2
    {
        const uint4* src = (const uint4*)Wt2;
#pragma unroll
        for (int i = 0; i < 16; i++) {
            int idx = tid + i*256;
            int r = idx >> 5, q = idx & 31;
            *(uint4*)&W32[r*ASW + q*4] = src[idx];
        }
    }
    // epilogue 1: relu(d + b1) -> hi/lo bf16 into A rows
#pragma unroll
    for (int nt = 0; nt < 8; nt++) {
        int c = cg*64 + nt*8 + t4*2;
        int w = c >> 1;
        float bv0 = sb1[c], bv1 = sb1[c+1];
#pragma unroll
        for (int hl = 0; hl < 2; hl++) {
            float* dd = hl ? d1[nt] : d0[nt];
            int rlo = hl ? ar2 : ar0;
            int rhi = hl ? ar3 : ar1;
            float v0 = dd[0] + bv0;
            float v1 = dd[1] + bv1;
            float v2 = dd[2] + bv0;
            float v3 = dd[3] + bv1;
            v0 = v0 > 0.f ? v0 : 0.f;
            v1 = v1 > 0.f ? v1 : 0.f;
            v2 = v2 > 0.f ? v2 : 0.f;
            v3 = v3 > 0.f ? v3 : 0.f;
            uint32_t h0 = bf16pair(v0, v1);
            uint32_t h1 = bf16pair(v2, v3);
            float2 f0 = __bfloat1622float2(*(__nv_bfloat162*)&h0);
            float2 f1 = __bfloat1622float2(*(__nv_bfloat162*)&h1);
            uint32_t l0 = bf16pair(v0 - f0.x, v1 - f0.y);
            uint32_t l1 = bf16pair(v2 - f1.x, v3 - f1.y);
            A32[rlo + w]      = h0;
            A32[rlo + 64 + w] = l0;
            A32[rhi + w]      = h1;
            A32[rhi + 64 + w] = l1;
            dd[0]=0.f; dd[1]=0.f; dd[2]=0.f; dd[3]=0.f;
        }
    }
    __syncthreads();

    // ---------- GEMM2 ----------
#pragma unroll
    for (int term = 0; term < 3; term++) {
#pragma unroll
        for (int s = 0; s < 8; s++) {
            int aw = abase[term] + s*8;
            int ww = wbase[term] + s*8;
            uint32_t a0 = A32[ar0 + aw + t4];
            uint32_t a1 = A32[ar1 + aw + t4];
            uint32_t a2 = A32[ar0 + aw + 4 + t4];
            uint32_t a3 = A32[ar1 + aw + 4 + t4];
            uint32_t a4 = A32[ar2 + aw + t4];
            uint32_t a5 = A32[ar3 + aw + t4];
            uint32_t a6 = A32[ar2 + aw + 4 + t4];
            uint32_t a7 = A32[ar3 + aw + 4 + t4];
#pragma unroll
            for (int nt = 0; nt < 8; nt++) {
                int n = cg*64 + nt*8 + g;
                uint32_t b0 = W32[n*ASW + ww + t4];
                uint32_t b1r = W32[n*ASW + ww + 4 + t4];
                mma16816(d0[nt], a0, a1, a2, a3, b0, b1r);
                mma16816(d1[nt], a4, a5, a6, a7, b0, b1r);
            }
        }
    }
    __syncthreads();   // done reading A (bf16) before fp32 overwrite

    // epilogue 2: relu(d + b2) -> fp32 into A region
    float* Af = (float*)A32;
    {
#pragma unroll
        for (int nt = 0; nt < 8; nt++) {
            int c = cg*64 + nt*8 + t4*2;
            float bv0 = sb2[c], bv1 = sb2[c+1];
#pragma unroll
            for (int hl = 0; hl < 2; hl++) {
                float* dd = hl ? d1[nt] : d0[nt];
                int rowA = rg*32 + g + (hl ? 16 : 0);
                int rowB = rowA + 8;
                float v0 = dd[0] + bv0;
                float v1 = dd[1] + bv1;
                float v2 = dd[2] + bv0;
                float v3 = dd[3] + bv1;
                v0 = v0 > 0.f ? v0 : 0.f;
                v1 = v1 > 0.f ? v1 : 0.f;
                v2 = v2 > 0.f ? v2 : 0.f;
                v3 = v3 > 0.f ? v3 : 0.f;
                if (rowbase + rowA >= NN) { v0 = 0.f; v1 = 0.f; }
                if (rowbase + rowB >= NN) { v2 = 0.f; v3 = 0.f; }
                *(float2*)&Af[rowA*ASW + c] = make_float2(v0, v1);
                *(float2*)&Af[rowB*ASW + c] = make_float2(v2, v3);
            }
        }
    }
    __syncthreads();

    // per-column stats (2 threads per column, 64 rows each)
    {
        int col = tid & 127;
        int half = tid >> 7;
        float s = 0.f, q = 0.f;
#pragma unroll 8
        for (int r = half*64; r < half*64 + 64; r++) {
            float x = Af[r*ASW + col];
            s += x; q += x*x;
        }
        atomicAdd(&g_colsum[br*HH + col], (double)s);
        atomicAdd(&g_colsq[br*HH + col], (double)q);
    }
    // coalesced store (warp per row): fp16 only
#pragma unroll
    for (int i = 0; i < 16; i++) {
        int r = wid + 8*i;
        int gr = rowbase + r;
        if (gr < NN) {
            float4 v = *(const float4*)&Af[r*ASW + lane*4];
            ((uint2*)(out16 + gr*128))[lane] = f4toh4(v);
        }
    }

    // ---------- fused BN finalize: last block (across both branches) computes scale/shift ----------
    __syncthreads();
    int* flag = (int*)sb1;   // sb1 dead now
    __threadfence();
    if (tid == 0) {
        int prev = atomicAdd(&g_ctr[layer], 1);
        flag[0] = (prev == 2*(int)gridDim.x - 1) ? 1 : 0;
    }
    __syncthreads();
    if (flag[0]) {
        __threadfence();
        int t = tid;            // 0..255 covers both branches
        int b2r = t >> 7, c = t & 127;
        const float* gamma = b2r ? gB : gA;
        const float* beta  = b2r ? btB : btA;
        double mu  = g_colsum[t] / (double)NN;
        double var = g_colsq[t] / (double)NN - mu*mu;
        if (var < 0.0) var = 0.0;
        float inv = rsqrtf((float)var + BN_EPS);
        float s = gamma[c] * inv;
        g_scale[t] = s;
        g_shift[t] = beta[c] - (float)mu * s;
        g_colsum[t] = 0.0;
        g_colsq[t] = 0.0;
    }
}

// ---------------- pool & heads ----------------
__global__ void k_pool2() {
    int g = blockIdx.x, br = blockIdx.y, c = threadIdx.x;
    const __half* h = g_h16[br];
    float* pool = br ? g_poolB : g_poolA;
    int s = g_gstart[g], e = g_gstart[g+1];
    float sc = g_scale[br*HH + c], sh = g_shift[br*HH + c];
    float acc = 0.f;
    for (int n = s; n < e; n++) acc += __half2float(h[n*128 + c]);
    float cnt = (float)(e - s);
    float cl = cnt < 1.f ? 1.f : cnt;
    pool[g*128 + c] = (acc*sc + cnt*sh) / cl;
}
__global__ void k_head1(const float* __restrict__ lin1_w, const float* __restrict__ lin1_b,
                        const float* __restrict__ lin2_w, const float* __restrict__ lin2_b,
                        const float* __restrict__ disc_w, float* __restrict__ outp)
{
    __shared__ float px[128];
    __shared__ float cat[256];
    __shared__ float h1[128];
    __shared__ float zz[OUTC];
    int g = blockIdx.x;
    int c = threadIdx.x;
    px[c] = g_poolB[g*128 + c];
    cat[c] = g_poolA[g*128 + c];
    cat[128 + c] = px[c];
    __syncthreads();
    float acc = 0.f;
    for (int e = 0; e < 128; e++) acc += disc_w[c*128 + e] * px[e];
    g_V[g*128 + c] = acc;
    float a2 = lin1_b[c];
    for (int k = 0; k < 256; k++) a2 += cat[k] * lin1_w[k*128 + c];
    h1[c] = a2 > 0.f ? a2 : 0.f;
    __syncthreads();
    if (c < OUTC) {
        float z = lin2_b[c];
        for (int k = 0; k < 128; k++) z += h1[k] * lin2_w[k*OUTC + c];
        zz[c] = z;
    }
    __syncthreads();
    if (c == 0) {
        float m = -1e30f;
        for (int o = 0; o < OUTC; o++) m = fmaxf(m, zz[o]);
        float s = 0.f;
        for (int o = 0; o < OUTC; o++) s += expf(zz[o] - m);
        float lse = logf(s) + m;
        for (int o = 0; o < OUTC; o++) outp[g*OUTC + o] = zz[o] - lse;
    }
}
__global__ void k_head2(const float* __restrict__ disc_b, float* __restrict__ outp) {
    int wid = (blockIdx.x*blockDim.x + threadIdx.x) >> 5;
    int lane = threadIdx.x & 31;
    if (wid >= 2*GG) return;
    int which = wid >> 6;
    int g = wid & 63;
    int gs = (which == 0) ? g : (g == 32 ? 30 : 63 - g);
    const float* a = &g_poolB[g*128];
    const float* v = &g_V[gs*128];
    float s = 0.f;
    for (int e = lane; e < 128; e += 32) s += a[e] * v[e];
#pragma unroll
    for (int off = 16; off > 0; off >>= 1) s += __shfl_down_sync(0xffffffffu, s, off);
    if (lane == 0) outp[GG*OUTC + which*GG + g] = s + disc_b[0];
}

// ---------------- launch ----------------
extern "C" void kernel_launch(void* const* d_in, const int* in_sizes, int n_in,
                              void* d_out, int out_size)
{
    (void)in_sizes; (void)n_in; (void)out_size;
    const float* x     = (const float*)d_in[0];
    const int*   ei    = (const int*)d_in[1];
    const int*   src   = ei;
    const int*   dst   = ei + EE;
    const int*   batch = (const int*)d_in[2];
    const float* W1a = (const float*)d_in[3];  const float* b1a = (const float*)d_in[4];
    const float* W2a = (const float*)d_in[5];  const float* b2a = (const float*)d_in[6];
    const float* ga  = (const float*)d_in[7];  const float* bta = (const float*)d_in[8];
    const float* W1b = (const float*)d_in[9];  const float* b1b = (const float*)d_in[10];
    const float* W2b = (const float*)d_in[11]; const float* b2b = (const float*)d_in[12];
    const float* gb  = (const float*)d_in[13]; const float* btb = (const float*)d_in[14];
    const float* lin1_w = (const float*)d_in[15]; const float* lin1_b = (const float*)d_in[16];
    const float* lin2_w = (const float*)d_in[17]; const float* lin2_b = (const float*)d_in[18];
    const float* disc_w = (const float*)d_in[19]; const float* disc_b = (const float*)d_in[20];
    float* outp = (float*)d_out;

    cudaFuncSetAttribute(k_mlp_mma, cudaFuncAttributeMaxDynamicSharedMemorySize, SMEM_BYTES);

    // CSR build + W/x prep
    k_init<<<(NN+391)/392, 392>>>();
    k_hist<<<(EE+255)/256, 256>>>(dst);
    k_scan1<<<NB_SCAN, 1024>>>();
    k_scan2<<<1, 128>>>();
    k_scan3<<<(NN+255)/256, 256>>>();
    k_fill<<<(EE+255)/256, 256>>>(src, dst);
    k_gstart<<<1, 96>>>(batch);
    k_wprep<<<768, 256>>>(W1a, W2a, W1b, W2b);
    k_xprep<<<(NN*HH/4 + 255)/256, 256>>>(x);

    const int mlp_bx = (NN + 127) / 128;
    const int gather_bx = (NN*32 + 255) / 256;   // 1 node per warp
    const dim3 mlp_grid(mlp_bx, 2);
    const dim3 gather_grid(gather_bx, 2);

    // layer 1 (shared gather of x in fp16)
    k_gather1<<<gather_bx, 256>>>();
    k_mlp_mma<<<mlp_grid, 256, SMEM_BYTES>>>(1, 0, b1a, b2a, b1b, b2b, ga, bta, gb, btb);

    // layers 2-3 (BN finalize fused into MLP)
    for (int l = 1; l < 3; l++) {
        k_gather2<<<gather_grid, 256>>>();
        k_mlp_mma<<<mlp_grid, 256, SMEM_BYTES>>>(0, l, b1a, b2a, b1b, b2b,
            ga + l*HH, bta + l*HH, gb + l*HH, btb + l*HH);
    }

    k_pool2<<<dim3(GG, 2), 128>>>();
    k_head1<<<GG, 128>>>(lin1_w, lin1_b, lin2_w, lin2_b, disc_w, outp);
    k_head2<<<16, 256>>>(disc_b, outp);
}

// round 16
// speedup vs baseline: 1.1162x; 1.0429x over previous
#include <cuda_runtime.h>
#include <cuda_bf16.h>
#include <cuda_fp16.h>
#include <cstdint>
#include <math.h>

#define NN 100000
#define EE 1600000
#define GG 64
#define HH 128
#define OUTC 10
#define BN_EPS 1e-5f
#define NB_SCAN 98   // ceil(100000/1024)

#define ASW 132                  // padded row stride in u32 words

// ---- k_mlp_mma smem layout (dynamic): A + W1 + W2 staged upfront ----
#define AS_OFF 0                 // u32[128][132]
#define W1_OFF 67584             // u32[128][132]
#define W2_OFF 135168            // u32[128][132]
#define SB1_OFF 202752
#define SB2_OFF 203264
#define SMEM_BYTES 203776

// ---------------- scratch (static device globals; no allocation) ----------------
__device__ __align__(256) __half g_agg16[2][NN*HH]; // fp16 MLP inputs
__device__ __align__(256) __half g_h16[2][NN*HH];   // fp16 layer outputs (gather + pool reads)
__device__ __align__(256) __half g_h16x[NN*HH];     // fp16 copy of x
// per mat (12): [n:128][256 bf16] : k 0-127 = hi, 128-255 = lo   (Wt[n][k] = W[k][n])
__device__ __align__(256) __nv_bfloat16 g_Wt[12*32768];
__device__ int g_deg[NN];
__device__ int g_rowstart[NN+1];
__device__ int g_cursor[NN];
__device__ int g_csrsrc[EE];
__device__ int g_bsum[NB_SCAN];
__device__ int g_gstart[GG+1];
__device__ int g_ctr[8];
__device__ __align__(16) float g_scale[3*HH];
__device__ __align__(16) float g_shift[3*HH];
__device__ double g_colsum[2*HH];
__device__ double g_colsq[2*HH];
__device__ float g_poolA[GG*HH];
__device__ float g_poolB[GG*HH];
__device__ float g_V[GG*HH];

// ---------------- helpers ----------------
__device__ __forceinline__ void mma16816(float* dd, uint32_t a0, uint32_t a1, uint32_t a2, uint32_t a3,
                                         uint32_t b0, uint32_t b1) {
    asm volatile(
        "mma.sync.aligned.m16n8k16.row.col.f32.bf16.bf16.f32 "
        "{%0,%1,%2,%3}, {%4,%5,%6,%7}, {%8,%9}, {%0,%1,%2,%3};\n"
        : "+f"(dd[0]), "+f"(dd[1]), "+f"(dd[2]), "+f"(dd[3])
        : "r"(a0), "r"(a1), "r"(a2), "r"(a3), "r"(b0), "r"(b1));
}
__device__ __forceinline__ uint32_t bf16pair(float x, float y) {
    __nv_bfloat162 h = __float22bfloat162_rn(make_float2(x, y));
    return *(uint32_t*)&h;
}
__device__ __forceinline__ float4 h4tof4(uint2 u) {
    __half2 p0 = *(__half2*)&u.x;
    __half2 p1 = *(__half2*)&u.y;
    float2 f0 = __half22float2(p0);
    float2 f1 = __half22float2(p1);
    return make_float4(f0.x, f0.y, f1.x, f1.y);
}
__device__ __forceinline__ uint2 f4toh4(float4 v) {
    __half2 a = __floats2half2_rn(v.x, v.y);
    __half2 b = __floats2half2_rn(v.z, v.w);
    return make_uint2(*(uint32_t*)&a, *(uint32_t*)&b);
}

// ---------------- CSR build ----------------
__global__ void k_init() {   // zero deg + affine identity + zero stats + counters
    int i = blockIdx.x*blockDim.x + threadIdx.x;
    if (i < NN) g_deg[i] = 0;
    if (blockIdx.x == 0) {
        int t = threadIdx.x;
        if (t < 3*HH) { g_scale[t] = 1.f; g_shift[t] = 0.f; }
        if (t < 2*HH) { g_colsum[t] = 0.0; g_colsq[t] = 0.0; }
        if (t < 8) g_ctr[t] = 0;
    }
}
__global__ void k_hist(const int* __restrict__ dst) {
    int e = blockIdx.x*blockDim.x + threadIdx.x;
    if (e < EE) atomicAdd(&g_deg[dst[e]], 1);
}
__global__ void k_scan1() {
    __shared__ int sm[1024];
    int tid = threadIdx.x;
    int i = blockIdx.x*1024 + tid;
    int v = (i < NN) ? g_deg[i] : 0;
    sm[tid] = v;
    __syncthreads();
    for (int off = 1; off < 1024; off <<= 1) {
        int t = (tid >= off) ? sm[tid-off] : 0;
        __syncthreads();
        sm[tid] += t;
        __syncthreads();
    }
    if (i < NN) g_rowstart[i] = sm[tid] - v;
    if (tid == 1023) g_bsum[blockIdx.x] = sm[1023];
}
__global__ void k_scan2() {
    __shared__ int sm[128];
    int t = threadIdx.x;
    int v = (t < NB_SCAN) ? g_bsum[t] : 0;
    sm[t] = v;
    __syncthreads();
    for (int off = 1; off < 128; off <<= 1) {
        int u = (t >= off) ? sm[t-off] : 0;
        __syncthreads();
        sm[t] += u;
        __syncthreads();
    }
    if (t < NB_SCAN) g_bsum[t] = sm[t] - v;
}
__global__ void k_scan3() {
    int i = blockIdx.x*blockDim.x + threadIdx.x;
    if (i < NN) {
        int v = g_rowstart[i] + g_bsum[i >> 10];
        g_rowstart[i] = v;
        g_cursor[i] = v;
    }
    if (i == 0) g_rowstart[NN] = EE;
}
__global__ void k_fill(const int* __restrict__ src, const int* __restrict__ dst) {
    int e = blockIdx.x*blockDim.x + threadIdx.x;
    if (e < EE) {
        int d = dst[e];
        int p = atomicAdd(&g_cursor[d], 1);
        g_csrsrc[p] = src[e];
    }
}
__global__ void k_gstart(const int* __restrict__ batch) {
    int t = threadIdx.x;
    if (t > GG) return;
    int lo = 0, hi = NN;
    while (lo < hi) { int mid = (lo+hi) >> 1; if (batch[mid] < t) lo = mid+1; else hi = mid; }
    g_gstart[t] = lo;
}
// convert x -> fp16
__global__ void k_xprep(const float* __restrict__ xp) {
    int i = blockIdx.x*blockDim.x + threadIdx.x;
    if (i >= NN*HH/4) return;
    float4 v = ((const float4*)xp)[i];
    ((uint2*)g_h16x)[i] = f4toh4(v);
}

// convert all 12 W matrices to transposed/split bf16: g_Wt[mat][n][k(hi) | 128+k(lo)]
__global__ void k_wprep(const float* __restrict__ W1a, const float* __restrict__ W2a,
                        const float* __restrict__ W1b, const float* __restrict__ W2b) {
    int m = blockIdx.x*blockDim.x + threadIdx.x;
    if (m >= 12*16384) return;
    int mat = m >> 14;
    int elem = m & 16383;
    int k = elem >> 7, n = elem & 127;
    int br = mat / 6, rem = mat % 6, l = rem >> 1, g = rem & 1;
    const float* W = g ? (br ? W2b : W2a) : (br ? W1b : W1a);
    float w = W[l*16384 + k*128 + n];
    __nv_bfloat16 hi = __float2bfloat16(w);
    __nv_bfloat16 lo = __float2bfloat16(w - __bfloat162float(hi));
    g_Wt[mat*32768 + n*256 + k]       = hi;
    g_Wt[mat*32768 + n*256 + 128 + k] = lo;
}

// ---------------- gathers (fp16 reads + fp16 agg writes, 1 node per warp) ----------------
__global__ void k_gather1() {
    int gw = (blockIdx.x*blockDim.x + threadIdx.x) >> 5;
    int lane = threadIdx.x & 31;
    if (gw >= NN) return;
    const uint2* __restrict__ h2 = (const uint2*)g_h16x;
    int rs = g_rowstart[gw], re = g_rowstart[gw+1];
    float4 acc = h4tof4(h2[gw*32 + lane]);   // self term
    int j = rs;
    for (; j + 4 <= re; j += 4) {
        int s0 = g_csrsrc[j], s1 = g_csrsrc[j+1], s2 = g_csrsrc[j+2], s3 = g_csrsrc[j+3];
        float4 v0 = h4tof4(h2[s0*32 + lane]);
        float4 v1 = h4tof4(h2[s1*32 + lane]);
        float4 v2 = h4tof4(h2[s2*32 + lane]);
        float4 v3 = h4tof4(h2[s3*32 + lane]);
        acc.x += (v0.x + v1.x) + (v2.x + v3.x);
        acc.y += (v0.y + v1.y) + (v2.y + v3.y);
        acc.z += (v0.z + v1.z) + (v2.z + v3.z);
        acc.w += (v0.w + v1.w) + (v2.w + v3.w);
    }
    for (; j < re; j++) {
        int s = g_csrsrc[j];
        float4 v = h4tof4(h2[s*32 + lane]);
        acc.x += v.x; acc.y += v.y; acc.z += v.z; acc.w += v.w;
    }
    ((uint2*)g_agg16[0])[gw*32 + lane] = f4toh4(acc);
}
__global__ void k_gather2() {
    int gw = (blockIdx.x*blockDim.x + threadIdx.x) >> 5;
    int lane = threadIdx.x & 31;
    if (gw >= NN) return;
    int br = blockIdx.y;
    const uint2* __restrict__ h2 = (const uint2*)g_h16[br];
    int rs = g_rowstart[gw], re = g_rowstart[gw+1];
    float4 acc = h4tof4(h2[gw*32 + lane]);
    int j = rs;
    for (; j + 4 <= re; j += 4) {
        int s0 = g_csrsrc[j], s1 = g_csrsrc[j+1], s2 = g_csrsrc[j+2], s3 = g_csrsrc[j+3];
        float4 v0 = h4tof4(h2[s0*32 + lane]);
        float4 v1 = h4tof4(h2[s1*32 + lane]);
        float4 v2 = h4tof4(h2[s2*32 + lane]);
        float4 v3 = h4tof4(h2[s3*32 + lane]);
        acc.x += (v0.x + v1.x) + (v2.x + v3.x);
        acc.y += (v0.y + v1.y) + (v2.y + v3.y);
        acc.z += (v0.z + v1.z) + (v2.z + v3.z);
        acc.w += (v0.w + v1.w) + (v2.w + v3.w);
    }
    for (; j < re; j++) {
        int s = g_csrsrc[j];
        float4 v = h4tof4(h2[s*32 + lane]);
        acc.x += v.x; acc.y += v.y; acc.z += v.z; acc.w += v.w;
    }
    float4 sc = ((const float4*)(g_scale + br*HH))[lane];
    float4 sh = ((const float4*)(g_shift + br*HH))[lane];
    float cf = (float)(re - rs + 1);
    float4 o;
    o.x = acc.x*sc.x + cf*sh.x;
    o.y = acc.y*sc.y + cf*sh.y;
    o.z = acc.z*sc.z + cf*sh.z;
    o.w = acc.w*sc.w + cf*sh.w;
    ((uint2*)g_agg16[br])[gw*32 + lane] = f4toh4(o);
}

// ---------------- HMMA fused MLP + fused BN finalize (warp = 32 rows x 64 cols) ----------------
// grid (mlp_bx, 2): blockIdx.y = branch. fp16 in / fp16 out. W1+W2 staged upfront.
__global__ void __launch_bounds__(256, 1)
k_mlp_mma(int aggShared, int layer,
          const float* __restrict__ b1a_, const float* __restrict__ b2a_,
          const float* __restrict__ b1b_, const float* __restrict__ b2b_,
          const float* __restrict__ gA, const float* __restrict__ btA,
          const float* __restrict__ gB, const float* __restrict__ btB)
{
    extern __shared__ char smem[];
    uint32_t* A32 = (uint32_t*)(smem + AS_OFF);
    uint32_t* W1s = (uint32_t*)(smem + W1_OFF);
    uint32_t* W2s = (uint32_t*)(smem + W2_OFF);
    float* sb1 = (float*)(smem + SB1_OFF);
    float* sb2 = (float*)(smem + SB2_OFF);
    const int tid = threadIdx.x, wid = tid >> 5, lane = tid & 31;
    const int g = lane >> 2, t4 = lane & 3;
    const int rg = wid >> 1;
    const int cg = wid & 1;
    const int br = blockIdx.y;
    const int rowbase = blockIdx.x * 128;
    const float* b1 = (br ? b1b_ : b1a_) + layer*HH;
    const float* b2 = (br ? b2b_ : b2a_) + layer*HH;
    const __half* Agg = g_agg16[aggShared ? 0 : br];
    __half* out16 = g_h16[br];
    const __nv_bfloat16* Wt1 = &g_Wt[(br*6 + layer*2 + 0)*32768];
    const __nv_bfloat16* Wt2 = &g_Wt[(br*6 + layer*2 + 1)*32768];

    if (tid < 128) { sb1[tid] = b1[tid]; sb2[tid] = b2[tid]; }

    // stage W1 + W2 upfront: 128 rows x 32 uint4 per row each
    {
        const uint4* s1 = (const uint4*)Wt1;
        const uint4* s2 = (const uint4*)Wt2;
#pragma unroll
        for (int i = 0; i < 16; i++) {
            int idx = tid + i*256;
            int r = idx >> 5, q = idx & 31;
            *(uint4*)&W1s[r*ASW + q*4] = s1[idx];
            *(uint4*)&W2s[r*ASW + q*4] = s2[idx];
        }
    }
    // stage A from fp16 agg (warp per row, coalesced)
#pragma unroll
    for (int i = 0; i < 16; i++) {
        int r = wid + 8*i;
        int grow = rowbase + r;
        float4 v = (grow < NN) ? h4tof4(((const uint2*)Agg)[grow*32 + lane]) : make_float4(0.f,0.f,0.f,0.f);
        uint32_t h01 = bf16pair(v.x, v.y);
        uint32_t h23 = bf16pair(v.z, v.w);
        float2 f01 = __bfloat1622float2(*(__nv_bfloat162*)&h01);
        float2 f23 = __bfloat1622float2(*(__nv_bfloat162*)&h23);
        uint32_t l01 = bf16pair(v.x - f01.x, v.y - f01.y);
        uint32_t l23 = bf16pair(v.z - f23.x, v.w - f23.y);
        *(uint2*)&A32[r*ASW + lane*2]      = make_uint2(h01, h23);
        *(uint2*)&A32[r*ASW + 64 + lane*2] = make_uint2(l01, l23);
    }
    __syncthreads();

    const int abase[3] = {0, 64, 0};
    const int wbase[3] = {0, 0, 64};
    const int r0 = rg*32 + g;
    const int ar0 = r0*ASW, ar1 = (r0+8)*ASW, ar2 = (r0+16)*ASW, ar3 = (r0+24)*ASW;

    float d0[8][4], d1[8][4];
#pragma unroll
    for (int nt = 0; nt < 8; nt++) {
        d0[nt][0]=0.f; d0[nt][1]=0.f; d0[nt][2]=0.f; d0[nt][3]=0.f;
        d1[nt][0]=0.f; d1[nt][1]=0.f; d1[nt][2]=0.f; d1[nt][3]=0.f;
    }

    // ---------- GEMM1 ----------
#pragma unroll
    for (int term = 0; term < 3; term++) {
#pragma unroll
        for (int s = 0; s < 8; s++) {
            int aw = abase[term] + s*8;
            int ww = wbase[term] + s*8;
            uint32_t a0 = A32[ar0 + aw + t4];
            uint32_t a1 = A32[ar1 + aw + t4];
            uint32_t a2 = A32[ar0 + aw + 4 + t4];
            uint32_t a3 = A32[ar1 + aw + 4 + t4];
            uint32_t a4 = A32[ar2 + aw + t4];
            uint32_t a5 = A32[ar3 + aw + t4];
            uint32_t a6 = A32[ar2 + aw + 4 + t4];
            uint32_t a7 = A32[ar3 + aw + 4 + t4];
#pragma unroll
            for (int nt = 0; nt < 8; nt++) {
                int n = cg*64 + nt*8 + g;
                uint32_t b0 = W1s[n*ASW + ww + t4];
                uint32_t b1r = W1s[n*ASW + ww + 4 + t4];
                mma16816(d0[nt], a0, a1, a2, a3, b0, b1r);
                mma16816(d1[nt], a4, a5, a6, a7, b0, b1r);
            }
        }
    }
    __syncthreads();   // all warps done with GEMM1 A-reads before epilogue-1 overwrites

    // epilogue 1: relu(d + b1) -> hi/lo bf16 into A rows
#pragma unroll
    for (int nt = 0; nt < 8; nt++) {
        int c = cg*64 + nt*8 + t4*2;
        int w = c >> 1;
        float bv0 = sb1[c], bv1 = sb1[c+1];
#pragma unroll
        for (int hl = 0; hl < 2; hl++) {
            float* dd = hl ? d1[nt] : d0[nt];
            int rlo = hl ? ar2 : ar0;
            int rhi = hl ? ar3 : ar1;
            float v0 = dd[0] + bv0;
            float v1 = dd[1] + bv1;
            float v2 = dd[2] + bv0;
            float v3 = dd[3] + bv1;
            v0 = v0 > 0.f ? v0 : 0.f;
            v1 = v1 > 0.f ? v1 : 0.f;
            v2 = v2 > 0.f ? v2 : 0.f;
            v3 = v3 > 0.f ? v3 : 0.f;
            uint32_t h0 = bf16pair(v0, v1);
            uint32_t h1 = bf16pair(v2, v3);
            float2 f0 = __bfloat1622float2(*(__nv_bfloat162*)&h0);
            float2 f1 = __bfloat1622float2(*(__nv_bfloat162*)&h1);
            uint32_t l0 = bf16pair(v0 - f0.x, v1 - f0.y);
            uint32_t l1 = bf16pair(v2 - f1.x, v3 - f1.y);
            A32[rlo + w]      = h0;
            A32[rlo + 64 + w] = l0;
            A32[rhi + w]      = h1;
            A32[rhi + 64 + w] = l1;
            dd[0]=0.f; dd[1]=0.f; dd[2]=0.f; dd[3]=0.f;
        }
    }
    __syncthreads();

    // ---------- GEMM2 ----------
#pragma unroll
    for (int term = 0; term < 3; term++) {
#pragma unroll
        for (int s = 0; s < 8; s++) {
            int aw = abase[term] + s*8;
            int ww = wbase[term] + s*8;
            uint32_t a0 = A32[ar0 + aw + t4];
            uint32_t a1 = A32[ar1 + aw + t4];
            uint32_t a2 = A32[ar0 + aw + 4 + t4];
            uint32_t a3 = A32[ar1 + aw + 4 + t4];
            uint32_t a4 = A32[ar2 + aw + t4];
            uint32_t a5 = A32[ar3 + aw + t4];
            uint32_t a6 = A32[ar2 + aw + 4 + t4];
            uint32_t a7 = A32[ar3 + aw + 4 + t4];
#pragma unroll
            for (int nt = 0; nt < 8; nt++) {
                int n = cg*64 + nt*8 + g;
                uint32_t b0 = W2s[n*ASW + ww + t4];
                uint32_t b1r = W2s[n*ASW + ww + 4 + t4];
                mma16816(d0[nt], a0, a1, a2, a3, b0, b1r);
                mma16816(d1[nt], a4, a5, a6, a7, b0, b1r);
            }
        }
    }
    __syncthreads();   // done reading A (bf16) before fp32 overwrite

    // epilogue 2: relu(d + b2) -> fp32 into A region
    float* Af = (float*)A32;
    {
#pragma unroll
        for (int nt = 0; nt < 8; nt++) {
            int c = cg*64 + nt*8 + t4*2;
            float bv0 = sb2[c], bv1 = sb2[c+1];
#pragma unroll
            for (int hl = 0; hl < 2; hl++) {
                float* dd = hl ? d1[nt] : d0[nt];
                int rowA = rg*32 + g + (hl ? 16 : 0);
                int rowB = rowA + 8;
                float v0 = dd[0] + bv0;
                float v1 = dd[1] + bv1;
                float v2 = dd[2] + bv0;
                float v3 = dd[3] + bv1;
                v0 = v0 > 0.f ? v0 : 0.f;
                v1 = v1 > 0.f ? v1 : 0.f;
                v2 = v2 > 0.f ? v2 : 0.f;
                v3 = v3 > 0.f ? v3 : 0.f;
                if (rowbase + rowA >= NN) { v0 = 0.f; v1 = 0.f; }
                if (rowbase + rowB >= NN) { v2 = 0.f; v3 = 0.f; }
                *(float2*)&Af[rowA*ASW + c] = make_float2(v0, v1);
                *(float2*)&Af[rowB*ASW + c] = make_float2(v2, v3);
            }
        }
    }
    __syncthreads();

    // per-column stats (2 threads per column, 64 rows each)
    {
        int col = tid & 127;
        int half = tid >> 7;
        float s = 0.f, q = 0.f;
#pragma unroll 8
        for (int r = half*64; r < half*64 + 64; r++) {
            float x = Af[r*ASW + col];
            s += x; q += x*x;
        }
        atomicAdd(&g_colsum[br*HH + col], (double)s);
        atomicAdd(&g_colsq[br*HH + col], (double)q);
    }
    // coalesced store (warp per row): fp16 only
#pragma unroll
    for (int i = 0; i < 16; i++) {
        int r = wid + 8*i;
        int gr = rowbase + r;
        if (gr < NN) {
            float4 v = *(const float4*)&Af[r*ASW + lane*4];
            ((uint2*)(out16 + gr*128))[lane] = f4toh4(v);
        }
    }

    // ---------- fused BN finalize: last block (across both branches) computes scale/shift ----------
    __syncthreads();
    int* flag = (int*)sb1;   // sb1 dead now
    __threadfence();
    if (tid == 0) {
        int prev = atomicAdd(&g_ctr[layer], 1);
        flag[0] = (prev == 2*(int)gridDim.x - 1) ? 1 : 0;
    }
    __syncthreads();
    if (flag[0]) {
        __threadfence();
        int t = tid;            // 0..255 covers both branches
        int b2r = t >> 7, c = t & 127;
        const float* gamma = b2r ? gB : gA;
        const float* beta  = b2r ? btB : btA;
        double mu  = g_colsum[t] / (double)NN;
        double var = g_colsq[t] / (double)NN - mu*mu;
        if (var < 0.0) var = 0.0;
        float inv = rsqrtf((float)var + BN_EPS);
        float s = gamma[c] * inv;
        g_scale[t] = s;
        g_shift[t] = beta[c] - (float)mu * s;
        g_colsum[t] = 0.0;
        g_colsq[t] = 0.0;
    }
}

// ---------------- pool & heads ----------------
__global__ void k_pool2() {
    int g = blockIdx.x, br = blockIdx.y, c = threadIdx.x;
    const __half* h = g_h16[br];
    float* pool = br ? g_poolB : g_poolA;
    int s = g_gstart[g], e = g_gstart[g+1];
    float sc = g_scale[br*HH + c], sh = g_shift[br*HH + c];
    float acc = 0.f;
    for (int n = s; n < e; n++) acc += __half2float(h[n*128 + c]);
    float cnt = (float)(e - s);
    float cl = cnt < 1.f ? 1.f : cnt;
    pool[g*128 + c] = (acc*sc + cnt*sh) / cl;
}
__global__ void k_head1(const float* __restrict__ lin1_w, const float* __restrict__ lin1_b,
                        const float* __restrict__ lin2_w, const float* __restrict__ lin2_b,
                        const float* __restrict__ disc_w, float* __restrict__ outp)
{
    __shared__ float px[128];
    __shared__ float cat[256];
    __shared__ float h1[128];
    __shared__ float zz[OUTC];
    int g = blockIdx.x;
    int c = threadIdx.x;
    px[c] = g_poolB[g*128 + c];
    cat[c] = g_poolA[g*128 + c];
    cat[128 + c] = px[c];
    __syncthreads();
    float acc = 0.f;
    for (int e = 0; e < 128; e++) acc += disc_w[c*128 + e] * px[e];
    g_V[g*128 + c] = acc;
    float a2 = lin1_b[c];
    for (int k = 0; k < 256; k++) a2 += cat[k] * lin1_w[k*128 + c];
    h1[c] = a2 > 0.f ? a2 : 0.f;
    __syncthreads();
    if (c < OUTC) {
        float z = lin2_b[c];
        for (int k = 0; k < 128; k++) z += h1[k] * lin2_w[k*OUTC + c];
        zz[c] = z;
    }
    __syncthreads();
    if (c == 0) {
        float m = -1e30f;
        for (int o = 0; o < OUTC; o++) m = fmaxf(m, zz[o]);
        float s = 0.f;
        for (int o = 0; o < OUTC; o++) s += expf(zz[o] - m);
        float lse = logf(s) + m;
        for (int o = 0; o < OUTC; o++) outp[g*OUTC + o] = zz[o] - lse;
    }
}
__global__ void k_head2(const float* __restrict__ disc_b, float* __restrict__ outp) {
    int wid = (blockIdx.x*blockDim.x + threadIdx.x) >> 5;
    int lane = threadIdx.x & 31;
    if (wid >= 2*GG) return;
    int which = wid >> 6;
    int g = wid & 63;
    int gs = (which == 0) ? g : (g == 32 ? 30 : 63 - g);
    const float* a = &g_poolB[g*128];
    const float* v = &g_V[gs*128];
    float s = 0.f;
    for (int e = lane; e < 128; e += 32) s += a[e] * v[e];
#pragma unroll
    for (int off = 16; off > 0; off >>= 1) s += __shfl_down_sync(0xffffffffu, s, off);
    if (lane == 0) outp[GG*OUTC + which*GG + g] = s + disc_b[0];
}

// ---------------- launch ----------------
extern "C" void kernel_launch(void* const* d_in, const int* in_sizes, int n_in,
                              void* d_out, int out_size)
{
    (void)in_sizes; (void)n_in; (void)out_size;
    const float* x     = (const float*)d_in[0];
    const int*   ei    = (const int*)d_in[1];
    const int*   src   = ei;
    const int*   dst   = ei + EE;
    const int*   batch = (const int*)d_in[2];
    const float* W1a = (const float*)d_in[3];  const float* b1a = (const float*)d_in[4];
    const float* W2a = (const float*)d_in[5];  const float* b2a = (const float*)d_in[6];
    const float* ga  = (const float*)d_in[7];  const float* bta = (const float*)d_in[8];
    const float* W1b = (const float*)d_in[9];  const float* b1b = (const float*)d_in[10];
    const float* W2b = (const float*)d_in[11]; const float* b2b = (const float*)d_in[12];
    const float* gb  = (const float*)d_in[13]; const float* btb = (const float*)d_in[14];
    const float* lin1_w = (const float*)d_in[15]; const float* lin1_b = (const float*)d_in[16];
    const float* lin2_w = (const float*)d_in[17]; const float* lin2_b = (const float*)d_in[18];
    const float* disc_w = (const float*)d_in[19]; const float* disc_b = (const float*)d_in[20];
    float* outp = (float*)d_out;

    cudaFuncSetAttribute(k_mlp_mma, cudaFuncAttributeMaxDynamicSharedMemorySize, SMEM_BYTES);

    // CSR build + W/x prep
    k_init<<<(NN+391)/392, 392>>>();
    k_hist<<<(EE+255)/256, 256>>>(dst);
    k_scan1<<<NB_SCAN, 1024>>>();
    k_scan2<<<1, 128>>>();
    k_scan3<<<(NN+255)/256, 256>>>();
    k_fill<<<(EE+255)/256, 256>>>(src, dst);
    k_gstart<<<1, 96>>>(batch);
    k_wprep<<<768, 256>>>(W1a, W2a, W1b, W2b);
    k_xprep<<<(NN*HH/4 + 255)/256, 256>>>(x);

    const int mlp_bx = (NN + 127) / 128;
    const int gather_bx = (NN*32 + 255) / 256;   // 1 node per warp
    const dim3 mlp_grid(mlp_bx, 2);
    const dim3 gather_grid(gather_bx, 2);

    // layer 1 (shared gather of x in fp16)
    k_gather1<<<gather_bx, 256>>>();
    k_mlp_mma<<<mlp_grid, 256, SMEM_BYTES>>>(1, 0, b1a, b2a, b1b, b2b, ga, bta, gb, btb);

    // layers 2-3 (BN finalize fused into MLP)
    for (int l = 1; l < 3; l++) {
        k_gather2<<<gather_grid, 256>>>();
        k_mlp_mma<<<mlp_grid, 256, SMEM_BYTES>>>(0, l, b1a, b2a, b1b, b2b,
            ga + l*HH, bta + l*HH, gb + l*HH, btb + l*HH);
    }

    k_pool2<<<dim3(GG, 2), 128>>>();
    k_head1<<<GG, 128>>>(lin1_w, lin1_b, lin2_w, lin2_b, disc_w, outp);
    k_head2<<<16, 256>>>(disc_b, outp);
}